// round 2
// baseline (speedup 1.0000x reference)
#include <cuda_runtime.h>

// Problem constants (CTCLayer_76038101008789)
#define BB 64
#define TT 512
#define VV 1296
#define SS 32
#define LL 65           // 2*S+1
#define LPAD 66         // padded row stride (even -> float2-aligned)
#define NEGV (-1e30f)

// Scratch (allocation-free rule: __device__ globals)
__device__ __align__(16) float g_lpext[(size_t)BB * TT * LPAD]; // ~8.6 MB, fits L2
__device__ float g_nll[BB];

__device__ __forceinline__ float lae2(float a, float b) {
    float m = fmaxf(a, b);
    return m + __logf(__expf(a - m) + __expf(b - m));
}
__device__ __forceinline__ float lae3(float a, float b, float c) {
    float m = fmaxf(fmaxf(a, b), c);
    return m + __logf(__expf(a - m) + __expf(b - m) + __expf(c - m));
}

// ---------------------------------------------------------------------------
// Kernel 1: per (b,t) row: lse = logsumexp(logits[b,t,:]),
//           lp_ext[b,t,s] = logits[b,t,ext(b,s)] - lse  (s = 0..64)
// One block per row; 128 threads; vectorized float4 loads (1296 = 324 float4).
// ---------------------------------------------------------------------------
__global__ __launch_bounds__(128) void k_lse_gather(
    const float* __restrict__ logits,
    const int* __restrict__ targets)
{
    int row = blockIdx.x;          // b*TT + t
    int b   = row >> 9;            // / TT
    const float* rp = logits + (size_t)row * VV;
    const float4* rp4 = (const float4*)rp;
    int tid = threadIdx.x;

    float4 v0 = rp4[tid];
    float4 v1 = rp4[tid + 128];
    float4 v2;
    if (tid + 256 < 324) v2 = rp4[tid + 256];
    else                 v2 = make_float4(NEGV, NEGV, NEGV, NEGV);

    float mx = fmaxf(fmaxf(fmaxf(v0.x, v0.y), fmaxf(v0.z, v0.w)),
                     fmaxf(fmaxf(v1.x, v1.y), fmaxf(v1.z, v1.w)));
    mx = fmaxf(mx, fmaxf(fmaxf(v2.x, v2.y), fmaxf(v2.z, v2.w)));

    __shared__ float red[4];
    __shared__ float bc_max, bc_sum;

    // block max
    #pragma unroll
    for (int o = 16; o > 0; o >>= 1) mx = fmaxf(mx, __shfl_xor_sync(0xffffffffu, mx, o));
    if ((tid & 31) == 0) red[tid >> 5] = mx;
    __syncthreads();
    if (tid == 0) bc_max = fmaxf(fmaxf(red[0], red[1]), fmaxf(red[2], red[3]));
    __syncthreads();
    mx = bc_max;

    // block sum of exp(x - mx)
    float se = __expf(v0.x - mx) + __expf(v0.y - mx) + __expf(v0.z - mx) + __expf(v0.w - mx)
             + __expf(v1.x - mx) + __expf(v1.y - mx) + __expf(v1.z - mx) + __expf(v1.w - mx)
             + __expf(v2.x - mx) + __expf(v2.y - mx) + __expf(v2.z - mx) + __expf(v2.w - mx);
    #pragma unroll
    for (int o = 16; o > 0; o >>= 1) se += __shfl_xor_sync(0xffffffffu, se, o);
    if ((tid & 31) == 0) red[tid >> 5] = se;
    __syncthreads();
    if (tid == 0) bc_sum = red[0] + red[1] + red[2] + red[3];
    __syncthreads();

    float lse = mx + __logf(bc_sum);

    if (tid < LL) {
        int lbl = (tid & 1) ? targets[b * SS + (tid >> 1)] : 0;
        lbl = min(max(lbl, 0), VV - 1);   // safety clamp (dtype surprises -> rel_err, not fault)
        g_lpext[(size_t)row * LPAD + tid] = rp[lbl] - lse;
    }
}

// ---------------------------------------------------------------------------
// Kernel 2: alpha recurrence. One warp per batch.
// Lane l holds alpha[2l], alpha[2l+1]; lane 31 additionally alpha[64].
// Only alpha[2l-1] (lane l-1's a1) is ever needed -> ONE shfl_up per step.
// Depth-4 software prefetch hides the L2 latency of lp_ext loads.
// ---------------------------------------------------------------------------
__global__ __launch_bounds__(32) void k_alpha(
    const int* __restrict__ targets,
    const int* __restrict__ ilen,
    const int* __restrict__ tlen)
{
    const unsigned FULL = 0xffffffffu;
    int b = blockIdx.x;
    int lane = threadIdx.x;

    int tgt  = targets[b * SS + lane];
    int tgtp = __shfl_up_sync(FULL, tgt, 1);
    bool skip1 = (lane > 0) && (tgt != tgtp);   // skip allowed for s = 2l+1

    const float* lp = g_lpext + (size_t)b * TT * LPAD;
    int Tb = ilen[b];
    int tl = tlen[b];

    float a0 = NEGV, a1 = NEGV, a2 = NEGV;
    if (lane == 0) { a0 = lp[0]; a1 = lp[1]; }

    float2 q0, q1, q2, q3;
    float  r0, r1, r2, r3;

#define PREF(Q, R, tt) do { if ((tt) < Tb) { \
        Q = *(const float2*)(lp + (size_t)(tt) * LPAD + 2 * lane); \
        R = lp[(size_t)(tt) * LPAD + 64]; } } while (0)

#define STEP(Q, R, tt) do { if ((tt) < Tb) { \
        float p1 = __shfl_up_sync(FULL, a1, 1); \
        if (lane == 0) p1 = NEGV; \
        float n0 = lae2(a0, p1) + Q.x;                       /* s=2l  (blank) */ \
        float n1 = lae3(a1, a0, skip1 ? p1 : NEGV) + Q.y;    /* s=2l+1 */ \
        float n2 = lae2(a2, a1) + R;                         /* s=64 (lane31) */ \
        a0 = n0; a1 = n1; a2 = n2; } } while (0)

    PREF(q0, r0, 1); PREF(q1, r1, 2); PREF(q2, r2, 3); PREF(q3, r3, 4);

    for (int t0 = 1; t0 < Tb; t0 += 4) {
        STEP(q0, r0, t0);     PREF(q0, r0, t0 + 4);
        STEP(q1, r1, t0 + 1); PREF(q1, r1, t0 + 5);
        STEP(q2, r2, t0 + 2); PREF(q2, r2, t0 + 6);
        STEP(q3, r3, t0 + 3); PREF(q3, r3, t0 + 7);
    }
#undef PREF
#undef STEP

    int s_end = 2 * tl;                                   // even (final blank)
    float e_a0 = __shfl_sync(FULL, a0, (s_end >> 1) & 31);
    float e_a2 = __shfl_sync(FULL, a2, 31);
    float l_end = (s_end >= 64) ? e_a2 : e_a0;
    float l_lab = __shfl_sync(FULL, a1, (tl - 1) & 31);   // s = 2tl-1

    float nll = -lae2(l_end, l_lab);
    if (!(nll < 1e29f)) nll = 0.0f;                       // zero_infinity (also NaN)
    if (lane == 0) g_nll[b] = nll / (float)tl;
}

// ---------------------------------------------------------------------------
// Kernel 3: mean over batch -> scalar output
// ---------------------------------------------------------------------------
__global__ __launch_bounds__(32) void k_reduce(float* __restrict__ out)
{
    int lane = threadIdx.x;
    float v = g_nll[lane] + g_nll[lane + 32];
    #pragma unroll
    for (int o = 16; o > 0; o >>= 1) v += __shfl_xor_sync(0xffffffffu, v, o);
    if (lane == 0) out[0] = v / (float)BB;
}

extern "C" void kernel_launch(void* const* d_in, const int* in_sizes, int n_in,
                              void* d_out, int out_size)
{
    const float* logits  = (const float*)d_in[0];
    const int*   targets = (const int*)d_in[1];
    const int*   ilen    = (const int*)d_in[2];
    const int*   tlen    = (const int*)d_in[3];

    k_lse_gather<<<BB * TT, 128>>>(logits, targets);
    k_alpha<<<BB, 32>>>(targets, ilen, tlen);
    k_reduce<<<1, 32>>>((float*)d_out);
}

// round 3
// speedup vs baseline: 1.8981x; 1.8981x over previous
#include <cuda_runtime.h>

// Problem constants (CTCLayer_76038101008789)
#define BB 64
#define TT 512
#define VV 1296
#define SS 32
#define LL 65           // 2*S+1
#define LPAD 66         // padded row stride (even -> float2-aligned)
#define NEGV (-1e30f)
#define FULLM 0xffffffffu

// Scratch (allocation-free rule: __device__ globals)
// Holds gathered PROBABILITIES exp(lp_ext) — linear domain. ~8.6 MB, fits L2.
__device__ __align__(16) float g_pext[(size_t)BB * TT * LPAD];
__device__ float g_nll[BB];

// ---------------------------------------------------------------------------
// Kernel 1: one WARP per (b,t) row. lse via warp reduction (no smem/syncthreads),
// then store P[s] = exp(logit[ext(s)] - mx) / sum  for s = 0..64.
// 1296 floats = 324 float4 = 32*10 + 4.
// ---------------------------------------------------------------------------
__global__ __launch_bounds__(256) void k_lse_gather(
    const float* __restrict__ logits,
    const int* __restrict__ targets)
{
    int row  = (blockIdx.x << 3) + (threadIdx.x >> 5);  // b*TT + t
    int lane = threadIdx.x & 31;
    int b    = row >> 9;                                 // / TT
    const float* rp = logits + (size_t)row * VV;
    const float4* rp4 = (const float4*)rp;

    float4 v[10];
    #pragma unroll
    for (int k = 0; k < 10; k++) v[k] = rp4[lane + (k << 5)];
    float4 ve = (lane < 4) ? rp4[320 + lane] : make_float4(NEGV, NEGV, NEGV, NEGV);

    float mx = fmaxf(fmaxf(ve.x, ve.y), fmaxf(ve.z, ve.w));
    #pragma unroll
    for (int k = 0; k < 10; k++)
        mx = fmaxf(mx, fmaxf(fmaxf(v[k].x, v[k].y), fmaxf(v[k].z, v[k].w)));
    #pragma unroll
    for (int o = 16; o > 0; o >>= 1) mx = fmaxf(mx, __shfl_xor_sync(FULLM, mx, o));

    float se = __expf(ve.x - mx) + __expf(ve.y - mx) + __expf(ve.z - mx) + __expf(ve.w - mx);
    #pragma unroll
    for (int k = 0; k < 10; k++)
        se += __expf(v[k].x - mx) + __expf(v[k].y - mx)
            + __expf(v[k].z - mx) + __expf(v[k].w - mx);
    #pragma unroll
    for (int o = 16; o > 0; o >>= 1) se += __shfl_xor_sync(FULLM, se, o);

    float inv = 1.0f / se;

    // gather + exp: 65 outputs, strided by lane
    #pragma unroll
    for (int s = lane; s < LL; s += 32) {
        int lbl = (s & 1) ? targets[b * SS + (s >> 1)] : 0;
        lbl = min(max(lbl, 0), VV - 1);
        g_pext[(size_t)row * LPAD + s] = __expf(rp[lbl] - mx) * inv;
    }
}

// ---------------------------------------------------------------------------
// Kernel 2: alpha recurrence in LINEAR domain with exact pow2 renormalization.
// One warp per batch. Lane l holds alpha[2l], alpha[2l+1]; lane 31 also alpha[64].
// Per step: 1 shfl + a handful of FADD/FFMA. Renorm (REDUX.MAX + pow2 scale)
// every 8 steps; exponent shifts accumulate exactly in an int.
// ---------------------------------------------------------------------------
__global__ __launch_bounds__(32) void k_alpha(
    const int* __restrict__ targets,
    const int* __restrict__ ilen,
    const int* __restrict__ tlen)
{
    int b = blockIdx.x;
    int lane = threadIdx.x;

    int tgt  = targets[b * SS + lane];
    int tgtp = __shfl_up_sync(FULLM, tgt, 1);
    float skipf = (lane > 0 && tgt != tgtp) ? 1.0f : 0.0f; // skip allowed for s=2l+1
    float mask0 = (lane > 0) ? 1.0f : 0.0f;

    const float* lp = g_pext + (size_t)b * TT * LPAD;
    int Tb = ilen[b];
    int tl = tlen[b];

    float a0 = 0.0f, a1 = 0.0f, a2 = 0.0f;
    if (lane == 0) { a0 = lp[0]; a1 = lp[1]; }
    int acc = 0;   // sum of log2(scales applied)

    float2 q0, q1, q2, q3, q4, q5, q6, q7;
    float  r0, r1, r2, r3, r4, r5, r6, r7;

#define PREF(Q, R, tt) do { if ((tt) < Tb) { \
        Q = *(const float2*)(lp + (size_t)(tt) * LPAD + 2 * lane); \
        R = lp[(size_t)(tt) * LPAD + 64]; } } while (0)

#define STEP(Q, R, tt) do { if ((tt) < Tb) { \
        float p1 = __shfl_up_sync(FULLM, a1, 1) * mask0; \
        float sQy = skipf * Q.y; \
        float n0 = fmaf(p1, Q.x, a0 * Q.x);              /* s=2l  (blank) */ \
        float n1 = fmaf(p1, sQy, (a1 + a0) * Q.y);       /* s=2l+1        */ \
        float n2 = (a2 + a1) * R;                        /* s=64 (lane31) */ \
        a0 = n0; a1 = n1; a2 = n2; } } while (0)

    PREF(q0, r0, 1); PREF(q1, r1, 2); PREF(q2, r2, 3); PREF(q3, r3, 4);
    PREF(q4, r4, 5); PREF(q5, r5, 6); PREF(q6, r6, 7); PREF(q7, r7, 8);

    for (int t0 = 1; t0 < Tb; t0 += 8) {
        STEP(q0, r0, t0);     PREF(q0, r0, t0 + 8);
        STEP(q1, r1, t0 + 1); PREF(q1, r1, t0 + 9);
        STEP(q2, r2, t0 + 2); PREF(q2, r2, t0 + 10);
        STEP(q3, r3, t0 + 3); PREF(q3, r3, t0 + 11);
        STEP(q4, r4, t0 + 4); PREF(q4, r4, t0 + 12);
        STEP(q5, r5, t0 + 5); PREF(q5, r5, t0 + 13);
        STEP(q6, r6, t0 + 6); PREF(q6, r6, t0 + 14);
        STEP(q7, r7, t0 + 7); PREF(q7, r7, t0 + 15);

        // renormalize: scale so warp-max lands in [2^80, 2^81), exact pow2
        float la2 = (lane == 31) ? a2 : 0.0f;
        float ml  = fmaxf(fmaxf(a0, a1), la2);
        int mb = __reduce_max_sync(FULLM, __float_as_int(ml)); // alpha >= 0
        int e  = mb >> 23;                                     // biased exponent
        int sb = 334 - e;                                      // 127 + (80 - (e-127))
        sb = min(max(sb, 1), 254);
        float s = __int_as_float(sb << 23);
        acc += sb - 127;
        a0 *= s; a1 *= s; a2 *= s;
    }
#undef PREF
#undef STEP

    int s_end = 2 * tl;                                  // even (final blank)
    float e_a0 = __shfl_sync(FULLM, a0, (s_end >> 1) & 31);
    float e_a2 = __shfl_sync(FULLM, a2, 31);
    float l_end = (s_end >= 64) ? e_a2 : e_a0;
    float l_lab = __shfl_sync(FULLM, a1, (tl - 1) & 31);  // s = 2tl-1

    float sum = l_end + l_lab;
    // true log p = log(sum) - acc*ln2   (double for exact exponent fold-back)
    double logtot = (double)__logf(sum) - (double)acc * 0.6931471805599453;
    float nll = (float)(-logtot);
    if (!(nll < 1e29f)) nll = 0.0f;                       // zero_infinity (also NaN/inf)
    if (lane == 0) g_nll[b] = nll / (float)tl;
}

// ---------------------------------------------------------------------------
// Kernel 3: mean over batch -> scalar output
// ---------------------------------------------------------------------------
__global__ __launch_bounds__(32) void k_reduce(float* __restrict__ out)
{
    int lane = threadIdx.x;
    float v = g_nll[lane] + g_nll[lane + 32];
    #pragma unroll
    for (int o = 16; o > 0; o >>= 1) v += __shfl_xor_sync(FULLM, v, o);
    if (lane == 0) out[0] = v / (float)BB;
}

extern "C" void kernel_launch(void* const* d_in, const int* in_sizes, int n_in,
                              void* d_out, int out_size)
{
    const float* logits  = (const float*)d_in[0];
    const int*   targets = (const int*)d_in[1];
    const int*   ilen    = (const int*)d_in[2];
    const int*   tlen    = (const int*)d_in[3];

    k_lse_gather<<<BB * TT / 8, 256>>>(logits, targets);
    k_alpha<<<BB, 32>>>(targets, ilen, tlen);
    k_reduce<<<1, 32>>>((float*)d_out);
}

// round 4
// speedup vs baseline: 1.9956x; 1.0514x over previous
#include <cuda_runtime.h>

// Problem constants (CTCLayer_76038101008789)
#define BB 64
#define TT 512
#define VV 1296
#define SS 32
#define LL 65           // 2*S+1
#define LPAD 66         // padded row stride (even -> float2-aligned)
#define NEGV (-1e30f)
#define FULLM 0xffffffffu

// Scratch. +16 padding rows so unguarded prefetch past t=Tb-1 stays in-bounds.
__device__ __align__(16) float g_pext[(size_t)(BB * TT + 16) * LPAD];
__device__ float g_nll[BB];

// ---------------------------------------------------------------------------
// Kernel 1: 64 threads (2 warps) per (b,t) row, 4 rows per 256-thread block.
// Row lse via warp reductions + tiny smem combine, then store
// P[s] = exp(logit[ext(s)] - mx) / sum for s = 0..64.
// 1296 floats = 324 float4 = 64*5 + 4.
// ---------------------------------------------------------------------------
__global__ __launch_bounds__(256) void k_lse_gather(
    const float* __restrict__ logits,
    const int* __restrict__ targets)
{
    int rgrp  = threadIdx.x >> 6;        // row within block: 0..3
    int t64   = threadIdx.x & 63;        // thread within row
    int wrow  = (threadIdx.x >> 5) & 1;  // warp within row: 0/1
    int row   = (blockIdx.x << 2) + rgrp;
    int b     = row >> 9;
    const float* rp = logits + (size_t)row * VV;
    const float4* rp4 = (const float4*)rp;

    float4 v[5];
    #pragma unroll
    for (int k = 0; k < 5; k++) v[k] = rp4[t64 + (k << 6)];
    float4 ve = (t64 < 4) ? rp4[320 + t64] : make_float4(NEGV, NEGV, NEGV, NEGV);

    float mx = fmaxf(fmaxf(ve.x, ve.y), fmaxf(ve.z, ve.w));
    #pragma unroll
    for (int k = 0; k < 5; k++)
        mx = fmaxf(mx, fmaxf(fmaxf(v[k].x, v[k].y), fmaxf(v[k].z, v[k].w)));
    #pragma unroll
    for (int o = 16; o > 0; o >>= 1) mx = fmaxf(mx, __shfl_xor_sync(FULLM, mx, o));

    __shared__ float smax[4][2], ssum[4][2];
    if ((threadIdx.x & 31) == 0) smax[rgrp][wrow] = mx;
    __syncthreads();
    mx = fmaxf(smax[rgrp][0], smax[rgrp][1]);

    float se = __expf(ve.x - mx) + __expf(ve.y - mx) + __expf(ve.z - mx) + __expf(ve.w - mx);
    #pragma unroll
    for (int k = 0; k < 5; k++)
        se += __expf(v[k].x - mx) + __expf(v[k].y - mx)
            + __expf(v[k].z - mx) + __expf(v[k].w - mx);
    #pragma unroll
    for (int o = 16; o > 0; o >>= 1) se += __shfl_xor_sync(FULLM, se, o);
    if ((threadIdx.x & 31) == 0) ssum[rgrp][wrow] = se;
    __syncthreads();
    float inv = 1.0f / (ssum[rgrp][0] + ssum[rgrp][1]);

    // gather + exp: 65 outputs per row, strided by t64
    #pragma unroll
    for (int s = t64; s < LL; s += 64) {
        int lbl = (s & 1) ? targets[b * SS + (s >> 1)] : 0;
        lbl = min(max(lbl, 0), VV - 1);
        g_pext[(size_t)row * LPAD + s] = __expf(rp[lbl] - mx) * inv;
    }
}

// ---------------------------------------------------------------------------
// Kernel 2: alpha recurrence, linear domain, exact pow2 renorm every 8 steps.
// One warp per batch. Lane l holds alpha[2l], alpha[2l+1]; lane 31 also alpha[64].
// Main loop: (Tb-1)/8 fully UNGUARDED 8-step blocks (no BSSY/BSYNC), prefetch
// runs into the padded scratch. Guarded tail handles the remainder.
// ---------------------------------------------------------------------------
__global__ __launch_bounds__(32) void k_alpha(
    const int* __restrict__ targets,
    const int* __restrict__ ilen,
    const int* __restrict__ tlen)
{
    int b = blockIdx.x;
    int lane = threadIdx.x;

    int tgt  = targets[b * SS + lane];
    int tgtp = __shfl_up_sync(FULLM, tgt, 1);
    float skipf = (lane > 0 && tgt != tgtp) ? 1.0f : 0.0f; // skip ok for s=2l+1
    float mask0 = (lane > 0) ? 1.0f : 0.0f;

    const float* lp = g_pext + (size_t)b * TT * LPAD;
    const float* pq = lp + 2 * lane;
    int Tb = ilen[b];
    int tl = tlen[b];

    float a0 = 0.0f, a1 = 0.0f, a2 = 0.0f;
    if (lane == 0) { a0 = lp[0]; a1 = lp[1]; }
    int acc = 0;   // sum of log2(scales applied)

    float2 q0, q1, q2, q3, q4, q5, q6, q7;
    float  r0, r1, r2, r3, r4, r5, r6, r7;

#define PREF_U(Q, R, tt) do { \
        Q = *(const float2*)(pq + (tt) * LPAD); \
        R = lp[(tt) * LPAD + 64]; } while (0)

#define STEP_U(Q, R) do { \
        float p1 = __shfl_up_sync(FULLM, a1, 1) * mask0; \
        float n0 = (a0 + p1) * Q.x;                      /* s=2l  (blank) */ \
        float n1 = fmaf(p1, skipf * Q.y, (a1 + a0) * Q.y); /* s=2l+1      */ \
        float n2 = (a2 + a1) * R;                        /* s=64 (lane31) */ \
        a0 = n0; a1 = n1; a2 = n2; } while (0)

    PREF_U(q0, r0, 1); PREF_U(q1, r1, 2); PREF_U(q2, r2, 3); PREF_U(q3, r3, 4);
    PREF_U(q4, r4, 5); PREF_U(q5, r5, 6); PREF_U(q6, r6, 7); PREF_U(q7, r7, 8);

    int nblk = (Tb - 1) >> 3;
    int t0 = 1;
    for (int blk = 0; blk < nblk; blk++) {
        STEP_U(q0, r0); PREF_U(q0, r0, t0 + 8);
        STEP_U(q1, r1); PREF_U(q1, r1, t0 + 9);
        STEP_U(q2, r2); PREF_U(q2, r2, t0 + 10);
        STEP_U(q3, r3); PREF_U(q3, r3, t0 + 11);
        STEP_U(q4, r4); PREF_U(q4, r4, t0 + 12);
        STEP_U(q5, r5); PREF_U(q5, r5, t0 + 13);
        STEP_U(q6, r6); PREF_U(q6, r6, t0 + 14);
        STEP_U(q7, r7); PREF_U(q7, r7, t0 + 15);
        t0 += 8;

        // renorm: scale so warp-max lands near 2^80; exact pow2, acc tracks it
        float la2 = (lane == 31) ? a2 : 0.0f;
        float ml  = fmaxf(fmaxf(a0, a1), la2);
        int mb = __reduce_max_sync(FULLM, __float_as_int(ml)); // alphas >= 0
        int e  = mb >> 23;
        int sb = min(max(334 - e, 1), 254);
        float s = __int_as_float(sb << 23);
        acc += sb - 127;
        a0 *= s; a1 *= s; a2 *= s;
    }

    // guarded tail: remaining (Tb-1)&7 steps, operands already prefetched
    if (t0     < Tb) STEP_U(q0, r0);
    if (t0 + 1 < Tb) STEP_U(q1, r1);
    if (t0 + 2 < Tb) STEP_U(q2, r2);
    if (t0 + 3 < Tb) STEP_U(q3, r3);
    if (t0 + 4 < Tb) STEP_U(q4, r4);
    if (t0 + 5 < Tb) STEP_U(q5, r5);
    if (t0 + 6 < Tb) STEP_U(q6, r6);
#undef PREF_U
#undef STEP_U

    int s_end = 2 * tl;                                  // even (final blank)
    float e_a0 = __shfl_sync(FULLM, a0, (s_end >> 1) & 31);
    float e_a2 = __shfl_sync(FULLM, a2, 31);
    float l_end = (s_end >= 64) ? e_a2 : e_a0;
    float l_lab = __shfl_sync(FULLM, a1, (tl - 1) & 31);  // s = 2tl-1

    float sum = l_end + l_lab;
    double logtot = (double)__logf(sum) - (double)acc * 0.6931471805599453;
    float nll = (float)(-logtot);
    if (!(nll < 1e29f)) nll = 0.0f;                       // zero_infinity (also NaN/inf)
    if (lane == 0) g_nll[b] = nll / (float)tl;
}

// ---------------------------------------------------------------------------
// Kernel 3: mean over batch -> scalar output
// ---------------------------------------------------------------------------
__global__ __launch_bounds__(32) void k_reduce(float* __restrict__ out)
{
    int lane = threadIdx.x;
    float v = g_nll[lane] + g_nll[lane + 32];
    #pragma unroll
    for (int o = 16; o > 0; o >>= 1) v += __shfl_xor_sync(FULLM, v, o);
    if (lane == 0) out[0] = v / (float)BB;
}

extern "C" void kernel_launch(void* const* d_in, const int* in_sizes, int n_in,
                              void* d_out, int out_size)
{
    const float* logits  = (const float*)d_in[0];
    const int*   targets = (const int*)d_in[1];
    const int*   ilen    = (const int*)d_in[2];
    const int*   tlen    = (const int*)d_in[3];

    k_lse_gather<<<BB * TT / 4, 256>>>(logits, targets);
    k_alpha<<<BB, 32>>>(targets, ilen, tlen);
    k_reduce<<<1, 32>>>((float*)d_out);
}

// round 5
// speedup vs baseline: 3.1338x; 1.5704x over previous
#include <cuda_runtime.h>
#include <cstdint>

// Problem constants (CTCLayer_76038101008789)
#define BB 64
#define TT 512
#define VV 1296
#define SS 32
#define LL 65            // 2*S+1
#define ROWF 36          // floats per (b,t) row: 32 target P + blank P + 3 pad (144B)
#define NEGV (-1e30f)
#define FULLM 0xffffffffu

// Scratch, padded by 80 rows so unguarded tile prefetch stays in-bounds.
__device__ __align__(16) float g_pt[(size_t)(BB * TT + 80) * ROWF]; // ~4.7 MB
__device__ float g_nll[BB];

// ---------------------------------------------------------------------------
// Kernel 1: one warp per (b,t) row (8 rows per 256-thread block).
// Warp-local logsumexp over V=1296 (10 float4/lane + 4 tail), then store
//   g_pt[row][l]  = exp(logit[tgt[l]] - mx) / sum   (coalesced 128B)
//   g_pt[row][32] = exp(logit[0]      - mx) / sum   (blank)
// ---------------------------------------------------------------------------
__global__ __launch_bounds__(256) void k_lse_gather(
    const float* __restrict__ logits,
    const int* __restrict__ targets)
{
    int row  = (blockIdx.x << 3) + (threadIdx.x >> 5);  // b*TT + t
    int lane = threadIdx.x & 31;
    int b    = row >> 9;
    const float* rp = logits + (size_t)row * VV;
    const float4* rp4 = (const float4*)rp;

    float4 v[10];
    #pragma unroll
    for (int k = 0; k < 10; k++) v[k] = rp4[lane + (k << 5)];
    float4 ve = (lane < 4) ? rp4[320 + lane] : make_float4(NEGV, NEGV, NEGV, NEGV);

    float mx = fmaxf(fmaxf(ve.x, ve.y), fmaxf(ve.z, ve.w));
    #pragma unroll
    for (int k = 0; k < 10; k++)
        mx = fmaxf(mx, fmaxf(fmaxf(v[k].x, v[k].y), fmaxf(v[k].z, v[k].w)));
    #pragma unroll
    for (int o = 16; o > 0; o >>= 1) mx = fmaxf(mx, __shfl_xor_sync(FULLM, mx, o));

    float se = __expf(ve.x - mx) + __expf(ve.y - mx) + __expf(ve.z - mx) + __expf(ve.w - mx);
    #pragma unroll
    for (int k = 0; k < 10; k++)
        se += __expf(v[k].x - mx) + __expf(v[k].y - mx)
            + __expf(v[k].z - mx) + __expf(v[k].w - mx);
    #pragma unroll
    for (int o = 16; o > 0; o >>= 1) se += __shfl_xor_sync(FULLM, se, o);

    float inv = 1.0f / se;

    int tgt = targets[b * SS + lane];
    tgt = min(max(tgt, 0), VV - 1);
    float pt = __expf(rp[tgt] - mx) * inv;

    size_t base = (size_t)row * ROWF;
    g_pt[base + lane] = pt;
    if (lane == 0) g_pt[base + 32] = __expf(rp[0] - mx) * inv;
}

// ---------------------------------------------------------------------------
// Kernel 2: alpha recurrence, linear domain, exact pow2 renorm every 8 steps.
// One warp per batch. Lane l holds alpha[2l], alpha[2l+1]; lane 31 also
// alpha[64]. Even states & s=64 are BLANK -> multiplier pb (uniform).
// 16-step tiles staged gmem->smem via cp.async.bulk + mbarrier ring (4 bufs,
// 3 tiles in flight); recurrence reads SMEM (conflict-free LDS).
// ---------------------------------------------------------------------------
#define TILE 16
#define TBYTES (TILE * ROWF * 4)    // 2304

__device__ __forceinline__ void mbar_wait(uint32_t mbar, uint32_t parity) {
    uint32_t done;
    asm volatile("{\n\t.reg .pred p;\n\t"
                 "mbarrier.try_wait.parity.shared.b64 p, [%1], %2;\n\t"
                 "selp.b32 %0, 1, 0, p;\n\t}"
                 : "=r"(done) : "r"(mbar), "r"(parity) : "memory");
    while (!done) {
        asm volatile("{\n\t.reg .pred p;\n\t"
                     "mbarrier.try_wait.parity.shared.b64 p, [%1], %2;\n\t"
                     "selp.b32 %0, 1, 0, p;\n\t}"
                     : "=r"(done) : "r"(mbar), "r"(parity) : "memory");
    }
}

__global__ __launch_bounds__(32) void k_alpha(
    const int* __restrict__ targets,
    const int* __restrict__ ilen,
    const int* __restrict__ tlen)
{
    __shared__ __align__(16) float buf[4][TILE * ROWF];
    __shared__ __align__(8) unsigned long long mbar[4];

    int b = blockIdx.x;
    int lane = threadIdx.x;

    uint32_t mb0 = (uint32_t)__cvta_generic_to_shared(&mbar[0]);
    if (lane == 0) {
        #pragma unroll
        for (int i = 0; i < 4; i++)
            asm volatile("mbarrier.init.shared.b64 [%0], 1;" :: "r"(mb0 + 8u * i) : "memory");
        asm volatile("fence.proxy.async.shared::cta;" ::: "memory");
    }
    __syncwarp();

    int tgt  = targets[b * SS + lane];
    int tgtp = __shfl_up_sync(FULLM, tgt, 1);
    float skipf = (lane > 0 && tgt != tgtp) ? 1.0f : 0.0f;
    float mask0 = (lane > 0) ? 1.0f : 0.0f;

    const float* lp = g_pt + (size_t)b * TT * ROWF;
    int Tb = ilen[b];
    int tl = tlen[b];

    float a0 = 0.0f, a1 = 0.0f, a2 = 0.0f;
    if (lane == 0) { a0 = lp[32]; a1 = lp[0]; }   // t=0: blank, first label
    int acc = 0;

    // issue tiles 0..2 (tile k covers t = 1+16k .. 16+16k)
    if (lane == 0) {
        #pragma unroll
        for (int k = 0; k < 3; k++) {
            uint32_t m = mb0 + 8u * k;
            uint32_t d = (uint32_t)__cvta_generic_to_shared(&buf[k][0]);
            const float* s = lp + (size_t)(1 + TILE * k) * ROWF;
            asm volatile("mbarrier.arrive.expect_tx.shared.b64 _, [%0], %1;"
                         :: "r"(m), "r"((uint32_t)TBYTES) : "memory");
            asm volatile("cp.async.bulk.shared::cluster.global.mbarrier::complete_tx::bytes "
                         "[%0], [%1], %2, [%3];"
                         :: "r"(d), "l"(s), "r"((uint32_t)TBYTES), "r"(m) : "memory");
        }
    }

#define STEP_S(q, pb) do { \
        float sq = skipf * (q); \
        float p1 = __shfl_up_sync(FULLM, a1, 1) * mask0; \
        float w  = (a1 + a0) * (q); \
        float n0 = (a0 + p1) * (pb); \
        float n1 = fmaf(p1, sq, w); \
        float n2 = (a2 + a1) * (pb); \
        a0 = n0; a1 = n1; a2 = n2; } while (0)

#define RENORM() do { \
        float la2 = (lane == 31) ? a2 : 0.0f; \
        float ml  = fmaxf(fmaxf(a0, a1), la2); \
        int mbv = __reduce_max_sync(FULLM, __float_as_int(ml)); \
        int sb = min(max(354 - (mbv >> 23), 1), 254); \
        float sc = __int_as_float(sb << 23); \
        acc += sb - 127; \
        a0 *= sc; a1 *= sc; a2 *= sc; } while (0)

    int nfull = (Tb - 1) >> 4;
    for (int k = 0; k < nfull; k++) {
        mbar_wait(mb0 + 8u * (k & 3), (k >> 2) & 1);
        const float* bp = &buf[k & 3][0];

        #pragma unroll
        for (int i = 0; i < TILE; i++) {
            float q  = bp[i * ROWF + lane];
            float pb = bp[i * ROWF + 32];
            STEP_S(q, pb);
            if (i == 7 || i == 15) RENORM();
        }

        // prefetch tile k+3 into slot (k+3)&3 (its old contents consumed at k-1)
        if (lane == 0) {
            int kn = k + 3;
            uint32_t m = mb0 + 8u * (kn & 3);
            uint32_t d = (uint32_t)__cvta_generic_to_shared(&buf[kn & 3][0]);
            const float* s = lp + (size_t)(1 + TILE * kn) * ROWF;
            asm volatile("mbarrier.arrive.expect_tx.shared.b64 _, [%0], %1;"
                         :: "r"(m), "r"((uint32_t)TBYTES) : "memory");
            asm volatile("cp.async.bulk.shared::cluster.global.mbarrier::complete_tx::bytes "
                         "[%0], [%1], %2, [%3];"
                         :: "r"(d), "l"(s), "r"((uint32_t)TBYTES), "r"(m) : "memory");
        }
    }

    // tail: remaining (Tb-1)&15 steps from tile nfull (already in flight)
    int rem = (Tb - 1) & 15;
    if (rem) {
        mbar_wait(mb0 + 8u * (nfull & 3), (nfull >> 2) & 1);
        const float* bp = &buf[nfull & 3][0];
        #pragma unroll
        for (int i = 0; i < 15; i++) {
            if (i < rem) {
                float q  = bp[i * ROWF + lane];
                float pb = bp[i * ROWF + 32];
                STEP_S(q, pb);
                if (i == 7) RENORM();
            }
        }
    }
#undef STEP_S
#undef RENORM

    int s_end = 2 * tl;                                   // even (final blank)
    float e_a0 = __shfl_sync(FULLM, a0, (s_end >> 1) & 31);
    float e_a2 = __shfl_sync(FULLM, a2, 31);
    float l_end = (s_end >= 64) ? e_a2 : e_a0;
    float l_lab = __shfl_sync(FULLM, a1, (tl - 1) & 31);  // s = 2tl-1

    float sum = l_end + l_lab;
    double logtot = (double)__logf(sum) - (double)acc * 0.6931471805599453;
    float nll = (float)(-logtot);
    if (!(nll < 1e29f)) nll = 0.0f;                       // zero_infinity (NaN/inf too)
    if (lane == 0) g_nll[b] = nll / (float)tl;
}

// ---------------------------------------------------------------------------
// Kernel 3: mean over batch -> scalar output
// ---------------------------------------------------------------------------
__global__ __launch_bounds__(32) void k_reduce(float* __restrict__ out)
{
    int lane = threadIdx.x;
    float v = g_nll[lane] + g_nll[lane + 32];
    #pragma unroll
    for (int o = 16; o > 0; o >>= 1) v += __shfl_xor_sync(FULLM, v, o);
    if (lane == 0) out[0] = v / (float)BB;
}

extern "C" void kernel_launch(void* const* d_in, const int* in_sizes, int n_in,
                              void* d_out, int out_size)
{
    const float* logits  = (const float*)d_in[0];
    const int*   targets = (const int*)d_in[1];
    const int*   ilen    = (const int*)d_in[2];
    const int*   tlen    = (const int*)d_in[3];

    k_lse_gather<<<BB * TT / 8, 256>>>(logits, targets);
    k_alpha<<<BB, 32>>>(targets, ilen, tlen);
    k_reduce<<<1, 32>>>((float*)d_out);
}